// round 5
// baseline (speedup 1.0000x reference)
#include <cuda_runtime.h>
#include <cuda_bf16.h>
#include <mma.h>
#include <cstdint>

using namespace nvcuda;

#define NN 100000
#define EE 1600000
#define NTILES (EE / 128)   // 12500, exact

// Scratch: per-node precomputed partial activations (layer-1 algebraic split).
__device__ __align__(256) float g_A[NN * 64];   // (W1a - W1b) @ x[n] + b1
__device__ __align__(256) float g_B[NN * 64];   // W1b @ x[n]

// Single dynamic-shared symbol for the whole TU.
extern __shared__ __align__(16) char dynsm[];

static __device__ __forceinline__ uint32_t pack_bf2(__nv_bfloat16 a, __nv_bfloat16 b) {
    __nv_bfloat162 v = __halves2bfloat162(a, b);
    return *reinterpret_cast<uint32_t*>(&v);
}

// ---------------------------------------------------------------------------
// Precompute A[n], B[n]: [N,64] x [64,128] fp32 GEMM, 64 nodes/block.
// ---------------------------------------------------------------------------
#define XS_STRIDE 68

__global__ void __launch_bounds__(256, 2)
pre_kernel(const float* __restrict__ x, const float* __restrict__ W1,
           const float* __restrict__ b1) {
    float* sm = (float*)dynsm;
    float* Ws = sm;            // 64*128 = 8192 floats: [k][j]
    float* xs = sm + 8192;     // 64*68  = 4352 floats

    int t = threadIdx.x;
    int n0 = blockIdx.x * 64;

    for (int i = t; i < 8192; i += 256) {
        int k = i >> 7, j = i & 127;
        float v;
        if (j < 64) v = __ldg(W1 + j * 128 + k) - __ldg(W1 + j * 128 + 64 + k);
        else        v = __ldg(W1 + (j - 64) * 128 + 64 + k);
        Ws[i] = v;
    }

    for (int i = t; i < 1024; i += 256) {
        int nl = i >> 4;
        int k  = (i & 15) << 2;
        int node = n0 + nl;
        float4 v = make_float4(0.f, 0.f, 0.f, 0.f);
        if (node < NN) v = *(const float4*)(x + node * 64 + k);
        *(float4*)(xs + nl * XS_STRIDE + k) = v;
    }
    __syncthreads();

    int jg = t & 31;  int j  = jg << 2;   // output col 0..124
    int ng = t >> 5;  int nb = ng << 3;   // node base 0..56

    float acc[8][4];
#pragma unroll
    for (int i = 0; i < 8; i++)
#pragma unroll
        for (int c = 0; c < 4; c++) acc[i][c] = 0.f;

#pragma unroll 4
    for (int k = 0; k < 64; k += 4) {
        float4 w0 = *(float4*)(Ws + (k + 0) * 128 + j);
        float4 w1 = *(float4*)(Ws + (k + 1) * 128 + j);
        float4 w2 = *(float4*)(Ws + (k + 2) * 128 + j);
        float4 w3 = *(float4*)(Ws + (k + 3) * 128 + j);
#pragma unroll
        for (int i = 0; i < 8; i++) {
            float4 xv = *(float4*)(xs + (nb + i) * XS_STRIDE + k);
            acc[i][0] = fmaf(xv.x, w0.x, acc[i][0]);
            acc[i][1] = fmaf(xv.x, w0.y, acc[i][1]);
            acc[i][2] = fmaf(xv.x, w0.z, acc[i][2]);
            acc[i][3] = fmaf(xv.x, w0.w, acc[i][3]);
            acc[i][0] = fmaf(xv.y, w1.x, acc[i][0]);
            acc[i][1] = fmaf(xv.y, w1.y, acc[i][1]);
            acc[i][2] = fmaf(xv.y, w1.z, acc[i][2]);
            acc[i][3] = fmaf(xv.y, w1.w, acc[i][3]);
            acc[i][0] = fmaf(xv.z, w2.x, acc[i][0]);
            acc[i][1] = fmaf(xv.z, w2.y, acc[i][1]);
            acc[i][2] = fmaf(xv.z, w2.z, acc[i][2]);
            acc[i][3] = fmaf(xv.z, w2.w, acc[i][3]);
            acc[i][0] = fmaf(xv.w, w3.x, acc[i][0]);
            acc[i][1] = fmaf(xv.w, w3.y, acc[i][1]);
            acc[i][2] = fmaf(xv.w, w3.z, acc[i][2]);
            acc[i][3] = fmaf(xv.w, w3.w, acc[i][3]);
        }
    }

#pragma unroll
    for (int i = 0; i < 8; i++) {
        int node = n0 + nb + i;
        if (node < NN) {
            float4 o;
            if (j < 64) {
                float4 bv = __ldg((const float4*)(b1 + j));
                o.x = acc[i][0] + bv.x; o.y = acc[i][1] + bv.y;
                o.z = acc[i][2] + bv.z; o.w = acc[i][3] + bv.w;
                *(float4*)(g_A + node * 64 + j) = o;
            } else {
                o.x = acc[i][0]; o.y = acc[i][1];
                o.z = acc[i][2]; o.w = acc[i][3];
                *(float4*)(g_B + node * 64 + (j - 64)) = o;
            }
        }
    }
}

// ---------------------------------------------------------------------------
// Edge kernel: wmma (HMMA) bf16 hi/lo-split GEMM, fp32 accumulate.
// Per 128-edge tile:
//   gather h = relu(A[r]+B[c]) fp32, split bf16 hi/lo into SMEM [row][88]
//   (K=0..63 data, K=64 = ones column for bias, K=65..79 zero pad)
//   W2 staged as col-major [j][88] hi/lo; row K=64 carries b2 hi/lo.
//   D = Ah*Bh + Ah*Bl + Al*Bh  (+ bias block), relu, store direct to gmem.
// 8 warps, each owns 16 edge rows x 64 outs.
// ---------------------------------------------------------------------------
#define HSTR 88                         // SMEM K-stride in bf16 elements
#define OFF_HH  0                       // 128*88*2 = 22528
#define OFF_HL  22528                   // 22528
#define OFF_W2H 45056                   // 64*88*2 = 11264
#define OFF_W2L 56320                   // 11264
#define EDGE_SMEM 67584

__global__ void __launch_bounds__(256)
edge_kernel(const int* __restrict__ ei, const float* __restrict__ W2,
            const float* __restrict__ b2, float* __restrict__ out) {
    __nv_bfloat16* hh  = (__nv_bfloat16*)(dynsm + OFF_HH);
    __nv_bfloat16* hl  = (__nv_bfloat16*)(dynsm + OFF_HL);
    __nv_bfloat16* w2h = (__nv_bfloat16*)(dynsm + OFF_W2H);
    __nv_bfloat16* w2l = (__nv_bfloat16*)(dynsm + OFF_W2L);

    const int t = threadIdx.x;
    const int w = t >> 5;

    // ---- one-time: stage W2 hi/lo (col-major [j][k]) + bias row + pads ----
    if (t < 64) {
        int j = t;
#pragma unroll
        for (int k = 0; k < 64; k++) {
            float f = __ldg(W2 + j * 64 + k);
            __nv_bfloat16 hi = __float2bfloat16(f);
            w2h[j * HSTR + k] = hi;
            w2l[j * HSTR + k] = __float2bfloat16(f - __bfloat162float(hi));
        }
        float bf = __ldg(b2 + j);
        __nv_bfloat16 bh = __float2bfloat16(bf);
        w2h[j * HSTR + 64] = bh;
        w2l[j * HSTR + 64] = __float2bfloat16(bf - __bfloat162float(bh));
#pragma unroll
        for (int k = 65; k < HSTR; k++) {
            w2h[j * HSTR + k] = __float2bfloat16(0.f);
            w2l[j * HSTR + k] = __float2bfloat16(0.f);
        }
    }
    // ---- one-time: h pad columns (K=64 ones / zeros; stay fixed) ----
    if (t < 128) {
        int r = t;
        hh[r * HSTR + 64] = __float2bfloat16(1.f);
        hl[r * HSTR + 64] = __float2bfloat16(0.f);
#pragma unroll
        for (int k = 65; k < HSTR; k++) {
            hh[r * HSTR + k] = __float2bfloat16(0.f);
            hl[r * HSTR + k] = __float2bfloat16(0.f);
        }
    }

    const int ge = t & 127;          // gather: edge row
    const int gk = (t >> 7) << 5;    // gather: k base 0 or 32

    for (int tile = blockIdx.x; tile < NTILES; tile += gridDim.x) {
        __syncthreads();   // previous tile's compute done reading hh/hl

        // ---- gather + relu + bf16 split: 2 threads per edge row ----
        {
            int e = tile * 128 + ge;
            int r = __ldg(ei + e);
            int c = __ldg(ei + EE + e);
            const float4* A4 = (const float4*)(g_A + (size_t)r * 64 + gk);
            const float4* B4 = (const float4*)(g_B + (size_t)c * 64 + gk);
            uint32_t base = ge * HSTR + gk;
#pragma unroll
            for (int c8 = 0; c8 < 4; c8++) {
                float4 a0 = __ldg(A4 + 2 * c8), a1 = __ldg(A4 + 2 * c8 + 1);
                float4 b0 = __ldg(B4 + 2 * c8), b1 = __ldg(B4 + 2 * c8 + 1);
                float f[8];
                f[0] = fmaxf(a0.x + b0.x, 0.f); f[1] = fmaxf(a0.y + b0.y, 0.f);
                f[2] = fmaxf(a0.z + b0.z, 0.f); f[3] = fmaxf(a0.w + b0.w, 0.f);
                f[4] = fmaxf(a1.x + b1.x, 0.f); f[5] = fmaxf(a1.y + b1.y, 0.f);
                f[6] = fmaxf(a1.z + b1.z, 0.f); f[7] = fmaxf(a1.w + b1.w, 0.f);
                uint32_t hi[4], lo[4];
#pragma unroll
                for (int p = 0; p < 4; p++) {
                    float f0 = f[2 * p], f1 = f[2 * p + 1];
                    __nv_bfloat16 h0 = __float2bfloat16(f0), h1 = __float2bfloat16(f1);
                    float r0 = f0 - __bfloat162float(h0);
                    float r1 = f1 - __bfloat162float(h1);
                    hi[p] = pack_bf2(h0, h1);
                    lo[p] = pack_bf2(__float2bfloat16(r0), __float2bfloat16(r1));
                }
                *(uint4*)(hh + base + c8 * 8) = make_uint4(hi[0], hi[1], hi[2], hi[3]);
                *(uint4*)(hl + base + c8 * 8) = make_uint4(lo[0], lo[1], lo[2], lo[3]);
            }
        }
        __syncthreads();

        // ---- wmma compute: warp w -> rows [16w, 16w+16) x 64 outs ----
        wmma::fragment<wmma::accumulator, 16, 16, 16, float> acc[4];
#pragma unroll
        for (int n = 0; n < 4; n++) wmma::fill_fragment(acc[n], 0.f);

        const __nv_bfloat16* ah_base = hh + w * 16 * HSTR;
        const __nv_bfloat16* al_base = hl + w * 16 * HSTR;

        wmma::fragment<wmma::matrix_a, 16, 16, 16, __nv_bfloat16, wmma::row_major> ah, al;
        wmma::fragment<wmma::matrix_b, 16, 16, 16, __nv_bfloat16, wmma::col_major> bh, bl;

#pragma unroll
        for (int ks = 0; ks < 4; ks++) {
            wmma::load_matrix_sync(ah, ah_base + ks * 16, HSTR);
            wmma::load_matrix_sync(al, al_base + ks * 16, HSTR);
#pragma unroll
            for (int n = 0; n < 4; n++) {
                wmma::load_matrix_sync(bh, w2h + n * 16 * HSTR + ks * 16, HSTR);
                wmma::load_matrix_sync(bl, w2l + n * 16 * HSTR + ks * 16, HSTR);
                wmma::mma_sync(acc[n], ah, bh, acc[n]);
                wmma::mma_sync(acc[n], ah, bl, acc[n]);
                wmma::mma_sync(acc[n], al, bh, acc[n]);
            }
        }
        // ---- bias block (K = 64..79): ones column x b2 hi/lo rows ----
        wmma::load_matrix_sync(ah, ah_base + 64, HSTR);
#pragma unroll
        for (int n = 0; n < 4; n++) {
            wmma::load_matrix_sync(bh, w2h + n * 16 * HSTR + 64, HSTR);
            wmma::load_matrix_sync(bl, w2l + n * 16 * HSTR + 64, HSTR);
            wmma::mma_sync(acc[n], ah, bh, acc[n]);
            wmma::mma_sync(acc[n], ah, bl, acc[n]);
        }

        // ---- relu (position-independent) + direct gmem store ----
        float* op = out + (size_t)(tile * 128 + w * 16) * 64;
#pragma unroll
        for (int n = 0; n < 4; n++) {
#pragma unroll
            for (int i = 0; i < acc[n].num_elements; i++)
                acc[n].x[i] = fmaxf(acc[n].x[i], 0.f);
            wmma::store_matrix_sync(op + n * 16, acc[n], 64, wmma::mem_row_major);
        }
    }
}

// ---------------------------------------------------------------------------
extern "C" void kernel_launch(void* const* d_in, const int* in_sizes, int n_in,
                              void* d_out, int out_size) {
    const float* x  = (const float*)d_in[0];
    const int*   ei = (const int*)d_in[1];     // int32 (JAX x64 disabled)
    const float* W1 = (const float*)d_in[2];
    const float* b1 = (const float*)d_in[3];
    const float* W2 = (const float*)d_in[4];
    const float* b2 = (const float*)d_in[5];
    float*       out = (float*)d_out;

    const int PRE_SMEM = (8192 + 64 * XS_STRIDE) * 4;   // 50176 B

    cudaFuncSetAttribute(pre_kernel,
                         cudaFuncAttributeMaxDynamicSharedMemorySize, PRE_SMEM);
    cudaFuncSetAttribute(edge_kernel,
                         cudaFuncAttributeMaxDynamicSharedMemorySize, EDGE_SMEM);

    pre_kernel<<<(NN + 63) / 64, 256, PRE_SMEM>>>(x, W1, b1);
    edge_kernel<<<444, 256, EDGE_SMEM>>>(ei, W2, b2, out);
}

// round 6
// speedup vs baseline: 1.0341x; 1.0341x over previous
#include <cuda_runtime.h>
#include <cuda_bf16.h>
#include <mma.h>
#include <cstdint>

using namespace nvcuda;

#define NN 100000
#define EE 1600000
#define NTILES (EE / 128)   // 12500, exact

// Scratch: per-node precomputed partial activations (layer-1 algebraic split).
__device__ __align__(256) float g_A[NN * 64];   // (W1a - W1b) @ x[n] + b1
__device__ __align__(256) float g_B[NN * 64];   // W1b @ x[n]

// Single dynamic-shared symbol for the whole TU.
extern __shared__ __align__(16) char dynsm[];

static __device__ __forceinline__ uint32_t pack_bf2(__nv_bfloat16 a, __nv_bfloat16 b) {
    __nv_bfloat162 v = __halves2bfloat162(a, b);
    return *reinterpret_cast<uint32_t*>(&v);
}

// ---------------------------------------------------------------------------
// Precompute A[n], B[n]: [N,64] x [64,128] fp32 GEMM, 128 nodes/block.
// ---------------------------------------------------------------------------
#define XS_STRIDE 68
#define PRE_SMEM ((8192 + 128 * XS_STRIDE) * 4)   // 67584 B

__global__ void __launch_bounds__(512)
pre_kernel(const float* __restrict__ x, const float* __restrict__ W1,
           const float* __restrict__ b1) {
    float* sm = (float*)dynsm;
    float* Ws = sm;            // 64*128 = 8192 floats: [k][j]
    float* xs = sm + 8192;     // 128*68 floats

    int t = threadIdx.x;
    int n0 = blockIdx.x * 128;

    for (int i = t; i < 8192; i += 512) {
        int k = i >> 7, j = i & 127;
        float v;
        if (j < 64) v = __ldg(W1 + j * 128 + k) - __ldg(W1 + j * 128 + 64 + k);
        else        v = __ldg(W1 + (j - 64) * 128 + 64 + k);
        Ws[i] = v;
    }

    for (int i = t; i < 2048; i += 512) {
        int nl = i >> 4;
        int k  = (i & 15) << 2;
        int node = n0 + nl;
        float4 v = make_float4(0.f, 0.f, 0.f, 0.f);
        if (node < NN) v = *(const float4*)(x + node * 64 + k);
        *(float4*)(xs + nl * XS_STRIDE + k) = v;
    }
    __syncthreads();

    int jg = t & 31;  int j  = jg << 2;   // output col 0..124
    int ng = t >> 5;  int nb = ng << 3;   // node base 0..120

    float acc[8][4];
#pragma unroll
    for (int i = 0; i < 8; i++)
#pragma unroll
        for (int c = 0; c < 4; c++) acc[i][c] = 0.f;

#pragma unroll 4
    for (int k = 0; k < 64; k += 4) {
        float4 w0 = *(float4*)(Ws + (k + 0) * 128 + j);
        float4 w1 = *(float4*)(Ws + (k + 1) * 128 + j);
        float4 w2 = *(float4*)(Ws + (k + 2) * 128 + j);
        float4 w3 = *(float4*)(Ws + (k + 3) * 128 + j);
#pragma unroll
        for (int i = 0; i < 8; i++) {
            float4 xv = *(float4*)(xs + (nb + i) * XS_STRIDE + k);
            acc[i][0] = fmaf(xv.x, w0.x, acc[i][0]);
            acc[i][1] = fmaf(xv.x, w0.y, acc[i][1]);
            acc[i][2] = fmaf(xv.x, w0.z, acc[i][2]);
            acc[i][3] = fmaf(xv.x, w0.w, acc[i][3]);
            acc[i][0] = fmaf(xv.y, w1.x, acc[i][0]);
            acc[i][1] = fmaf(xv.y, w1.y, acc[i][1]);
            acc[i][2] = fmaf(xv.y, w1.z, acc[i][2]);
            acc[i][3] = fmaf(xv.y, w1.w, acc[i][3]);
            acc[i][0] = fmaf(xv.z, w2.x, acc[i][0]);
            acc[i][1] = fmaf(xv.z, w2.y, acc[i][1]);
            acc[i][2] = fmaf(xv.z, w2.z, acc[i][2]);
            acc[i][3] = fmaf(xv.z, w2.w, acc[i][3]);
            acc[i][0] = fmaf(xv.w, w3.x, acc[i][0]);
            acc[i][1] = fmaf(xv.w, w3.y, acc[i][1]);
            acc[i][2] = fmaf(xv.w, w3.z, acc[i][2]);
            acc[i][3] = fmaf(xv.w, w3.w, acc[i][3]);
        }
    }

#pragma unroll
    for (int i = 0; i < 8; i++) {
        int node = n0 + nb + i;
        if (node < NN) {
            float4 o;
            if (j < 64) {
                float4 bv = __ldg((const float4*)(b1 + j));
                o.x = acc[i][0] + bv.x; o.y = acc[i][1] + bv.y;
                o.z = acc[i][2] + bv.z; o.w = acc[i][3] + bv.w;
                *(float4*)(g_A + node * 64 + j) = o;
            } else {
                o.x = acc[i][0]; o.y = acc[i][1];
                o.z = acc[i][2]; o.w = acc[i][3];
                *(float4*)(g_B + node * 64 + (j - 64)) = o;
            }
        }
    }
}

// ---------------------------------------------------------------------------
// Edge kernel: wmma bf16 hi/lo-split GEMM, software-pipelined.
// Double-buffered h (hi/lo) in SMEM. Per iteration:
//   issue LDGs + hsum=relu(A[r]+B[c]) for tile i+1   (latency overlaps mma)
//   wmma compute tile i from buf p  -> relu -> gmem
//   split hsum -> bf16 hi/lo -> buf p^1
//   one __syncthreads()
// K layout: 0..63 data, 64 = ones column (bias via b2 row in W2), 65..79 pad.
// ---------------------------------------------------------------------------
#define HSTR 88                         // SMEM K-stride in bf16 elements
#define HBUF 22528                      // bytes per hh or hl plane (128*88*2)
#define PBUF 45056                      // bytes per (hh,hl) pair
#define OFF_W2H 90112
#define OFF_W2L 101376
#define EDGE_SMEM 112640

__global__ void __launch_bounds__(256, 2)
edge_kernel(const int* __restrict__ ei, const float* __restrict__ W2,
            const float* __restrict__ b2, float* __restrict__ out) {
    __nv_bfloat16* w2h = (__nv_bfloat16*)(dynsm + OFF_W2H);
    __nv_bfloat16* w2l = (__nv_bfloat16*)(dynsm + OFF_W2L);

    const int t = threadIdx.x;
    const int w = t >> 5;

    // ---- one-time: stage W2 hi/lo (col-major [j][k]) + bias row + pads ----
    if (t < 64) {
        int j = t;
#pragma unroll
        for (int k = 0; k < 64; k++) {
            float f = __ldg(W2 + j * 64 + k);
            __nv_bfloat16 hi = __float2bfloat16(f);
            w2h[j * HSTR + k] = hi;
            w2l[j * HSTR + k] = __float2bfloat16(f - __bfloat162float(hi));
        }
        float bf = __ldg(b2 + j);
        __nv_bfloat16 bh = __float2bfloat16(bf);
        w2h[j * HSTR + 64] = bh;
        w2l[j * HSTR + 64] = __float2bfloat16(bf - __bfloat162float(bh));
#pragma unroll
        for (int k = 65; k < HSTR; k++) {
            w2h[j * HSTR + k] = __float2bfloat16(0.f);
            w2l[j * HSTR + k] = __float2bfloat16(0.f);
        }
    }
    // ---- one-time: h pad columns for BOTH buffers (K>=64: ones/zero) ----
    if (t < 128) {
#pragma unroll
        for (int p = 0; p < 2; p++) {
            __nv_bfloat16* hh = (__nv_bfloat16*)(dynsm + p * PBUF);
            __nv_bfloat16* hl = (__nv_bfloat16*)(dynsm + p * PBUF + HBUF);
            hh[t * HSTR + 64] = __float2bfloat16(1.f);
            hl[t * HSTR + 64] = __float2bfloat16(0.f);
#pragma unroll
            for (int k = 65; k < HSTR; k++) {
                hh[t * HSTR + k] = __float2bfloat16(0.f);
                hl[t * HSTR + k] = __float2bfloat16(0.f);
            }
        }
    }

    const int ge = t & 127;          // gather: edge row
    const int gk = (t >> 7) << 5;    // gather: k base 0 or 32

    // gather helpers -------------------------------------------------------
    auto gather_sum = [&](int tile, float* hsum) {
        int e = tile * 128 + ge;
        int r = __ldg(ei + e);
        int c = __ldg(ei + EE + e);
        const float4* A4 = (const float4*)(g_A + (size_t)r * 64 + gk);
        const float4* B4 = (const float4*)(g_B + (size_t)c * 64 + gk);
#pragma unroll
        for (int q = 0; q < 8; q++) {
            float4 a = __ldg(A4 + q);
            float4 b = __ldg(B4 + q);
            hsum[4 * q + 0] = fmaxf(a.x + b.x, 0.f);
            hsum[4 * q + 1] = fmaxf(a.y + b.y, 0.f);
            hsum[4 * q + 2] = fmaxf(a.z + b.z, 0.f);
            hsum[4 * q + 3] = fmaxf(a.w + b.w, 0.f);
        }
    };
    auto split_store = [&](const float* hsum, int p) {
        __nv_bfloat16* hh = (__nv_bfloat16*)(dynsm + p * PBUF);
        __nv_bfloat16* hl = (__nv_bfloat16*)(dynsm + p * PBUF + HBUF);
        uint32_t base = ge * HSTR + gk;
#pragma unroll
        for (int q = 0; q < 4; q++) {
            uint32_t hi[4], lo[4];
#pragma unroll
            for (int pp = 0; pp < 4; pp++) {
                float f0 = hsum[8 * q + 2 * pp], f1 = hsum[8 * q + 2 * pp + 1];
                __nv_bfloat16 h0 = __float2bfloat16(f0), h1 = __float2bfloat16(f1);
                float r0 = f0 - __bfloat162float(h0);
                float r1 = f1 - __bfloat162float(h1);
                hi[pp] = pack_bf2(h0, h1);
                lo[pp] = pack_bf2(__float2bfloat16(r0), __float2bfloat16(r1));
            }
            *(uint4*)(hh + base + q * 8) = make_uint4(hi[0], hi[1], hi[2], hi[3]);
            *(uint4*)(hl + base + q * 8) = make_uint4(lo[0], lo[1], lo[2], lo[3]);
        }
    };
    auto compute = [&](int tile, int p) {
        const __nv_bfloat16* hh = (const __nv_bfloat16*)(dynsm + p * PBUF);
        const __nv_bfloat16* hl = (const __nv_bfloat16*)(dynsm + p * PBUF + HBUF);

        wmma::fragment<wmma::accumulator, 16, 16, 16, float> acc[4];
#pragma unroll
        for (int n = 0; n < 4; n++) wmma::fill_fragment(acc[n], 0.f);

        const __nv_bfloat16* ah_base = hh + w * 16 * HSTR;
        const __nv_bfloat16* al_base = hl + w * 16 * HSTR;

        wmma::fragment<wmma::matrix_a, 16, 16, 16, __nv_bfloat16, wmma::row_major> ah, al;
        wmma::fragment<wmma::matrix_b, 16, 16, 16, __nv_bfloat16, wmma::col_major> bh, bl;

#pragma unroll
        for (int ks = 0; ks < 4; ks++) {
            wmma::load_matrix_sync(ah, ah_base + ks * 16, HSTR);
            wmma::load_matrix_sync(al, al_base + ks * 16, HSTR);
#pragma unroll
            for (int n = 0; n < 4; n++) {
                wmma::load_matrix_sync(bh, w2h + n * 16 * HSTR + ks * 16, HSTR);
                wmma::load_matrix_sync(bl, w2l + n * 16 * HSTR + ks * 16, HSTR);
                wmma::mma_sync(acc[n], ah, bh, acc[n]);
                wmma::mma_sync(acc[n], ah, bl, acc[n]);
                wmma::mma_sync(acc[n], al, bh, acc[n]);
            }
        }
        // bias block (K = 64..79): ones column x b2 hi/lo rows
        wmma::load_matrix_sync(ah, ah_base + 64, HSTR);
#pragma unroll
        for (int n = 0; n < 4; n++) {
            wmma::load_matrix_sync(bh, w2h + n * 16 * HSTR + 64, HSTR);
            wmma::load_matrix_sync(bl, w2l + n * 16 * HSTR + 64, HSTR);
            wmma::mma_sync(acc[n], ah, bh, acc[n]);
            wmma::mma_sync(acc[n], ah, bl, acc[n]);
        }

        float* op = out + (size_t)(tile * 128 + w * 16) * 64;
#pragma unroll
        for (int n = 0; n < 4; n++) {
#pragma unroll
            for (int i = 0; i < acc[n].num_elements; i++)
                acc[n].x[i] = fmaxf(acc[n].x[i], 0.f);
            wmma::store_matrix_sync(op + n * 16, acc[n], 64, wmma::mem_row_major);
        }
    };
    // ----------------------------------------------------------------------

    int tile = blockIdx.x;
    int p = 0;
    if (tile < NTILES) {
        float hs0[32];
        gather_sum(tile, hs0);
        split_store(hs0, 0);
    }
    __syncthreads();

    while (tile < NTILES) {
        int next = tile + gridDim.x;
        bool hn = next < NTILES;
        float hsum[32];
        if (hn) gather_sum(next, hsum);   // LDGs overlap the mma below
        compute(tile, p);
        if (hn) split_store(hsum, p ^ 1);
        __syncthreads();
        tile = next;
        p ^= 1;
    }
}

// ---------------------------------------------------------------------------
extern "C" void kernel_launch(void* const* d_in, const int* in_sizes, int n_in,
                              void* d_out, int out_size) {
    const float* x  = (const float*)d_in[0];
    const int*   ei = (const int*)d_in[1];     // int32 (JAX x64 disabled)
    const float* W1 = (const float*)d_in[2];
    const float* b1 = (const float*)d_in[3];
    const float* W2 = (const float*)d_in[4];
    const float* b2 = (const float*)d_in[5];
    float*       out = (float*)d_out;

    cudaFuncSetAttribute(pre_kernel,
                         cudaFuncAttributeMaxDynamicSharedMemorySize, PRE_SMEM);
    cudaFuncSetAttribute(edge_kernel,
                         cudaFuncAttributeMaxDynamicSharedMemorySize, EDGE_SMEM);

    pre_kernel<<<(NN + 127) / 128, 512, PRE_SMEM>>>(x, W1, b1);
    edge_kernel<<<296, 256, EDGE_SMEM>>>(ei, W2, b2, out);
}

// round 8
// speedup vs baseline: 1.6969x; 1.6410x over previous
#include <cuda_runtime.h>
#include <cuda_bf16.h>
#include <mma.h>
#include <cstdint>

using namespace nvcuda;

#define NN 100000
#define EE 1600000
#define NTILES (EE / 128)   // 12500, exact

__device__ __align__(256) float g_A[NN * 64];   // (W1a - W1b) @ x[n] + b1
__device__ __align__(256) float g_B[NN * 64];   // W1b @ x[n]

extern __shared__ __align__(16) char dynsm[];

static __device__ __forceinline__ uint32_t pack_bf2(__nv_bfloat16 a, __nv_bfloat16 b) {
    __nv_bfloat162 v = __halves2bfloat162(a, b);
    return *reinterpret_cast<uint32_t*>(&v);
}

// ---------------------------------------------------------------------------
// Precompute A[n], B[n]: [N,64] x [64,128] fp32 GEMM, 128 nodes/block.
// ---------------------------------------------------------------------------
#define XS_STRIDE 68
#define PRE_SMEM ((8192 + 128 * XS_STRIDE) * 4)   // 67584 B

__global__ void __launch_bounds__(512)
pre_kernel(const float* __restrict__ x, const float* __restrict__ W1,
           const float* __restrict__ b1) {
    float* sm = (float*)dynsm;
    float* Ws = sm;            // 64*128 floats: [k][j]
    float* xs = sm + 8192;     // 128*68 floats

    int t = threadIdx.x;
    int n0 = blockIdx.x * 128;

    for (int i = t; i < 8192; i += 512) {
        int k = i >> 7, j = i & 127;
        float v;
        if (j < 64) v = __ldg(W1 + j * 128 + k) - __ldg(W1 + j * 128 + 64 + k);
        else        v = __ldg(W1 + (j - 64) * 128 + 64 + k);
        Ws[i] = v;
    }
    for (int i = t; i < 2048; i += 512) {
        int nl = i >> 4;
        int k  = (i & 15) << 2;
        int node = n0 + nl;
        float4 v = make_float4(0.f, 0.f, 0.f, 0.f);
        if (node < NN) v = *(const float4*)(x + node * 64 + k);
        *(float4*)(xs + nl * XS_STRIDE + k) = v;
    }
    __syncthreads();

    int jg = t & 31;  int j  = jg << 2;
    int ng = t >> 5;  int nb = ng << 3;

    float acc[8][4];
#pragma unroll
    for (int i = 0; i < 8; i++)
#pragma unroll
        for (int c = 0; c < 4; c++) acc[i][c] = 0.f;

#pragma unroll 4
    for (int k = 0; k < 64; k += 4) {
        float4 w0 = *(float4*)(Ws + (k + 0) * 128 + j);
        float4 w1 = *(float4*)(Ws + (k + 1) * 128 + j);
        float4 w2 = *(float4*)(Ws + (k + 2) * 128 + j);
        float4 w3 = *(float4*)(Ws + (k + 3) * 128 + j);
#pragma unroll
        for (int i = 0; i < 8; i++) {
            float4 xv = *(float4*)(xs + (nb + i) * XS_STRIDE + k);
            acc[i][0] = fmaf(xv.x, w0.x, acc[i][0]);
            acc[i][1] = fmaf(xv.x, w0.y, acc[i][1]);
            acc[i][2] = fmaf(xv.x, w0.z, acc[i][2]);
            acc[i][3] = fmaf(xv.x, w0.w, acc[i][3]);
            acc[i][0] = fmaf(xv.y, w1.x, acc[i][0]);
            acc[i][1] = fmaf(xv.y, w1.y, acc[i][1]);
            acc[i][2] = fmaf(xv.y, w1.z, acc[i][2]);
            acc[i][3] = fmaf(xv.y, w1.w, acc[i][3]);
            acc[i][0] = fmaf(xv.z, w2.x, acc[i][0]);
            acc[i][1] = fmaf(xv.z, w2.y, acc[i][1]);
            acc[i][2] = fmaf(xv.z, w2.z, acc[i][2]);
            acc[i][3] = fmaf(xv.z, w2.w, acc[i][3]);
            acc[i][0] = fmaf(xv.w, w3.x, acc[i][0]);
            acc[i][1] = fmaf(xv.w, w3.y, acc[i][1]);
            acc[i][2] = fmaf(xv.w, w3.z, acc[i][2]);
            acc[i][3] = fmaf(xv.w, w3.w, acc[i][3]);
        }
    }

#pragma unroll
    for (int i = 0; i < 8; i++) {
        int node = n0 + nb + i;
        if (node < NN) {
            float4 o;
            if (j < 64) {
                float4 bv = __ldg((const float4*)(b1 + j));
                o.x = acc[i][0] + bv.x; o.y = acc[i][1] + bv.y;
                o.z = acc[i][2] + bv.z; o.w = acc[i][3] + bv.w;
                *(float4*)(g_A + node * 64 + j) = o;
            } else {
                o.x = acc[i][0]; o.y = acc[i][1];
                o.z = acc[i][2]; o.w = acc[i][3];
                *(float4*)(g_B + node * 64 + (j - 64)) = o;
            }
        }
    }
}

// ---------------------------------------------------------------------------
// Edge kernel v3: wmma bf16 hi/lo split.
//  - W2 fragments (8 data + 2 bias per warp's n-quarter) hoisted into
//    registers ONCE (zero per-tile B smem traffic).
//  - Warp mapping: w = rg*4 + nq. rg in {0,1} -> rows rg*64..+64 (4 rb),
//    nq in 0..3 -> cols nq*16..+16.
//  - Coalesced gather: indices staged in smem; 16 threads per edge row
//    (16 x float4 = contiguous 256B).
// K layout: 0..63 data, 64 = ones (bias), 65..79 zero pad.
// ---------------------------------------------------------------------------
#define HSTR 88
#define OFF_IDX 0                        // 256 ints = 1024 B
#define OFF_HH  1024                     // 128*88*2 = 22528
#define OFF_HL  (1024 + 22528)           // 22528
#define EDGE_SMEM (1024 + 45056)         // 46080 B

__global__ void __launch_bounds__(256, 2)
edge_kernel(const int* __restrict__ ei, const float* __restrict__ W2,
            const float* __restrict__ b2, float* __restrict__ out) {
    int* sidx = (int*)(dynsm + OFF_IDX);
    __nv_bfloat16* hh = (__nv_bfloat16*)(dynsm + OFF_HH);
    __nv_bfloat16* hl = (__nv_bfloat16*)(dynsm + OFF_HL);

    const int t = threadIdx.x;
    const int w = t >> 5;
    const int nq = w & 3;          // n quarter (cols nq*16..+16)
    const int rg = w >> 2;         // row group (rows rg*64..+64)

    // ---- stage W2 hi/lo into (reused) h area, load B fragments, then free it
    {
        __nv_bfloat16* w2h = hh;                    // 64*88 bf16 = 11264 B
        __nv_bfloat16* w2l = hh + 64 * HSTR;        // next 11264 B
        if (t < 64) {
            int j = t;
#pragma unroll
            for (int k = 0; k < 64; k++) {
                float f = __ldg(W2 + j * 64 + k);
                __nv_bfloat16 hi = __float2bfloat16(f);
                w2h[j * HSTR + k] = hi;
                w2l[j * HSTR + k] = __float2bfloat16(f - __bfloat162float(hi));
            }
            float bf = __ldg(b2 + j);
            __nv_bfloat16 bh = __float2bfloat16(bf);
            w2h[j * HSTR + 64] = bh;
            w2l[j * HSTR + 64] = __float2bfloat16(bf - __bfloat162float(bh));
#pragma unroll
            for (int k = 65; k < 80; k++) {
                w2h[j * HSTR + k] = __float2bfloat16(0.f);
                w2l[j * HSTR + k] = __float2bfloat16(0.f);
            }
        }
        __syncthreads();
        // fall through: fragments declared below read from w2h/w2l
    }

    wmma::fragment<wmma::matrix_b, 16, 16, 16, __nv_bfloat16, wmma::col_major>
        Bh[4], Bl[4], Bbh, Bbl;
    {
        const __nv_bfloat16* w2h = hh;
        const __nv_bfloat16* w2l = hh + 64 * HSTR;
#pragma unroll
        for (int ks = 0; ks < 4; ks++) {
            wmma::load_matrix_sync(Bh[ks], w2h + nq * 16 * HSTR + ks * 16, HSTR);
            wmma::load_matrix_sync(Bl[ks], w2l + nq * 16 * HSTR + ks * 16, HSTR);
        }
        wmma::load_matrix_sync(Bbh, w2h + nq * 16 * HSTR + 64, HSTR);
        wmma::load_matrix_sync(Bbl, w2l + nq * 16 * HSTR + 64, HSTR);
    }
    __syncthreads();

    // ---- one-time: h pad columns (64 = ones, 65..79 = zero) ----
    if (t < 128) {
        hh[t * HSTR + 64] = __float2bfloat16(1.f);
        hl[t * HSTR + 64] = __float2bfloat16(0.f);
#pragma unroll
        for (int k = 65; k < 80; k++) {
            hh[t * HSTR + k] = __float2bfloat16(0.f);
            hl[t * HSTR + k] = __float2bfloat16(0.f);
        }
    }
    __syncthreads();

    const int grp = t >> 4;        // 16 groups of 16 threads
    const int g   = t & 15;        // lane within group -> float4 index 0..15

    for (int tile = blockIdx.x; tile < NTILES; tile += gridDim.x) {
        // ---- stage indices (coalesced) ----
        sidx[t] = (t < 128) ? __ldg(ei + tile * 128 + t)
                            : __ldg(ei + EE + tile * 128 + (t - 128));
        __syncthreads();

        // ---- coalesced gather: 16 threads per edge row, 8 passes ----
#pragma unroll
        for (int p = 0; p < 8; p++) {
            int edge = p * 16 + grp;
            int r = sidx[edge];
            int c = sidx[128 + edge];
            float4 a = __ldg((const float4*)(g_A + (size_t)r * 64) + g);
            float4 b = __ldg((const float4*)(g_B + (size_t)c * 64) + g);
            float f0 = fmaxf(a.x + b.x, 0.f);
            float f1 = fmaxf(a.y + b.y, 0.f);
            float f2 = fmaxf(a.z + b.z, 0.f);
            float f3 = fmaxf(a.w + b.w, 0.f);
            __nv_bfloat16 h0 = __float2bfloat16(f0), h1 = __float2bfloat16(f1);
            __nv_bfloat16 h2 = __float2bfloat16(f2), h3 = __float2bfloat16(f3);
            uint2 hi = make_uint2(pack_bf2(h0, h1), pack_bf2(h2, h3));
            uint2 lo = make_uint2(
                pack_bf2(__float2bfloat16(f0 - __bfloat162float(h0)),
                         __float2bfloat16(f1 - __bfloat162float(h1))),
                pack_bf2(__float2bfloat16(f2 - __bfloat162float(h2)),
                         __float2bfloat16(f3 - __bfloat162float(h3))));
            *(uint2*)(hh + edge * HSTR + g * 4) = hi;
            *(uint2*)(hl + edge * HSTR + g * 4) = lo;
        }
        __syncthreads();

        // ---- compute: warp (rg, nq); 4 row-blocks processed in pairs ----
#pragma unroll
        for (int rbp = 0; rbp < 2; rbp++) {
            int rows0 = rg * 64 + rbp * 32;
            int rows1 = rows0 + 16;

            wmma::fragment<wmma::accumulator, 16, 16, 16, float> acc0, acc1;
            wmma::fill_fragment(acc0, 0.f);
            wmma::fill_fragment(acc1, 0.f);

            wmma::fragment<wmma::matrix_a, 16, 16, 16, __nv_bfloat16, wmma::row_major>
                ah0, al0, ah1, al1;

#pragma unroll
            for (int ks = 0; ks < 4; ks++) {
                wmma::load_matrix_sync(ah0, hh + rows0 * HSTR + ks * 16, HSTR);
                wmma::load_matrix_sync(al0, hl + rows0 * HSTR + ks * 16, HSTR);
                wmma::load_matrix_sync(ah1, hh + rows1 * HSTR + ks * 16, HSTR);
                wmma::load_matrix_sync(al1, hl + rows1 * HSTR + ks * 16, HSTR);
                wmma::mma_sync(acc0, ah0, Bh[ks], acc0);
                wmma::mma_sync(acc1, ah1, Bh[ks], acc1);
                wmma::mma_sync(acc0, ah0, Bl[ks], acc0);
                wmma::mma_sync(acc1, ah1, Bl[ks], acc1);
                wmma::mma_sync(acc0, al0, Bh[ks], acc0);
                wmma::mma_sync(acc1, al1, Bh[ks], acc1);
            }
            // bias block (ones column x b2 rows)
            wmma::load_matrix_sync(ah0, hh + rows0 * HSTR + 64, HSTR);
            wmma::load_matrix_sync(ah1, hh + rows1 * HSTR + 64, HSTR);
            wmma::mma_sync(acc0, ah0, Bbh, acc0);
            wmma::mma_sync(acc1, ah1, Bbh, acc1);
            wmma::mma_sync(acc0, ah0, Bbl, acc0);
            wmma::mma_sync(acc1, ah1, Bbl, acc1);

#pragma unroll
            for (int i = 0; i < acc0.num_elements; i++) {
                acc0.x[i] = fmaxf(acc0.x[i], 0.f);
                acc1.x[i] = fmaxf(acc1.x[i], 0.f);
            }
            float* op0 = out + (size_t)(tile * 128 + rows0) * 64 + nq * 16;
            float* op1 = out + (size_t)(tile * 128 + rows1) * 64 + nq * 16;
            wmma::store_matrix_sync(op0, acc0, 64, wmma::mem_row_major);
            wmma::store_matrix_sync(op1, acc1, 64, wmma::mem_row_major);
        }
        __syncthreads();   // compute done before next tile's gather overwrites
    }
}

// ---------------------------------------------------------------------------
extern "C" void kernel_launch(void* const* d_in, const int* in_sizes, int n_in,
                              void* d_out, int out_size) {
    const float* x  = (const float*)d_in[0];
    const int*   ei = (const int*)d_in[1];     // int32 (JAX x64 disabled)
    const float* W1 = (const float*)d_in[2];
    const float* b1 = (const float*)d_in[3];
    const float* W2 = (const float*)d_in[4];
    const float* b2 = (const float*)d_in[5];
    float*       out = (float*)d_out;

    cudaFuncSetAttribute(pre_kernel,
                         cudaFuncAttributeMaxDynamicSharedMemorySize, PRE_SMEM);
    cudaFuncSetAttribute(edge_kernel,
                         cudaFuncAttributeMaxDynamicSharedMemorySize, EDGE_SMEM);

    pre_kernel<<<(NN + 127) / 128, 512, PRE_SMEM>>>(x, W1, b1);
    edge_kernel<<<296, 256, EDGE_SMEM>>>(ei, W2, b2, out);
}

// round 11
// speedup vs baseline: 2.3094x; 1.3610x over previous
#include <cuda_runtime.h>
#include <cuda_bf16.h>
#include <mma.h>
#include <cstdint>

using namespace nvcuda;

#define NN 100000
#define EE 1600000
#define NT64 (EE / 64)      // 25000 64-edge tiles, exact

__device__ __align__(256) float g_A[NN * 64];   // (W1a - W1b) @ x[n] + b1
__device__ __align__(256) float g_B[NN * 64];   // W1b @ x[n]

extern __shared__ __align__(16) char dynsm[];

static __device__ __forceinline__ uint32_t pack_bf2(__nv_bfloat16 a, __nv_bfloat16 b) {
    __nv_bfloat162 v = __halves2bfloat162(a, b);
    return *reinterpret_cast<uint32_t*>(&v);
}

// ---------------------------------------------------------------------------
// Precompute A[n], B[n]: [N,64] x [64,128] fp32 GEMM, 128 nodes/block.
// ---------------------------------------------------------------------------
#define XS_STRIDE 68
#define PRE_SMEM ((8192 + 128 * XS_STRIDE) * 4)   // 67584 B

__global__ void __launch_bounds__(512)
pre_kernel(const float* __restrict__ x, const float* __restrict__ W1,
           const float* __restrict__ b1) {
    float* sm = (float*)dynsm;
    float* Ws = sm;            // 64*128 floats: [k][j]
    float* xs = sm + 8192;     // 128*68 floats

    int t = threadIdx.x;
    int n0 = blockIdx.x * 128;

    for (int i = t; i < 8192; i += 512) {
        int k = i >> 7, j = i & 127;
        float v;
        if (j < 64) v = __ldg(W1 + j * 128 + k) - __ldg(W1 + j * 128 + 64 + k);
        else        v = __ldg(W1 + (j - 64) * 128 + 64 + k);
        Ws[i] = v;
    }
    for (int i = t; i < 2048; i += 512) {
        int nl = i >> 4;
        int k  = (i & 15) << 2;
        int node = n0 + nl;
        float4 v = make_float4(0.f, 0.f, 0.f, 0.f);
        if (node < NN) v = *(const float4*)(x + node * 64 + k);
        *(float4*)(xs + nl * XS_STRIDE + k) = v;
    }
    __syncthreads();

    int jg = t & 31;  int j  = jg << 2;
    int ng = t >> 5;  int nb = ng << 3;

    float acc[8][4];
#pragma unroll
    for (int i = 0; i < 8; i++)
#pragma unroll
        for (int c = 0; c < 4; c++) acc[i][c] = 0.f;

#pragma unroll 4
    for (int k = 0; k < 64; k += 4) {
        float4 w0 = *(float4*)(Ws + (k + 0) * 128 + j);
        float4 w1 = *(float4*)(Ws + (k + 1) * 128 + j);
        float4 w2 = *(float4*)(Ws + (k + 2) * 128 + j);
        float4 w3 = *(float4*)(Ws + (k + 3) * 128 + j);
#pragma unroll
        for (int i = 0; i < 8; i++) {
            float4 xv = *(float4*)(xs + (nb + i) * XS_STRIDE + k);
            acc[i][0] = fmaf(xv.x, w0.x, acc[i][0]);
            acc[i][1] = fmaf(xv.x, w0.y, acc[i][1]);
            acc[i][2] = fmaf(xv.x, w0.z, acc[i][2]);
            acc[i][3] = fmaf(xv.x, w0.w, acc[i][3]);
            acc[i][0] = fmaf(xv.y, w1.x, acc[i][0]);
            acc[i][1] = fmaf(xv.y, w1.y, acc[i][1]);
            acc[i][2] = fmaf(xv.y, w1.z, acc[i][2]);
            acc[i][3] = fmaf(xv.y, w1.w, acc[i][3]);
            acc[i][0] = fmaf(xv.z, w2.x, acc[i][0]);
            acc[i][1] = fmaf(xv.z, w2.y, acc[i][1]);
            acc[i][2] = fmaf(xv.z, w2.z, acc[i][2]);
            acc[i][3] = fmaf(xv.z, w2.w, acc[i][3]);
            acc[i][0] = fmaf(xv.w, w3.x, acc[i][0]);
            acc[i][1] = fmaf(xv.w, w3.y, acc[i][1]);
            acc[i][2] = fmaf(xv.w, w3.z, acc[i][2]);
            acc[i][3] = fmaf(xv.w, w3.w, acc[i][3]);
        }
    }

#pragma unroll
    for (int i = 0; i < 8; i++) {
        int node = n0 + nb + i;
        if (node < NN) {
            float4 o;
            if (j < 64) {
                float4 bv = __ldg((const float4*)(b1 + j));
                o.x = acc[i][0] + bv.x; o.y = acc[i][1] + bv.y;
                o.z = acc[i][2] + bv.z; o.w = acc[i][3] + bv.w;
                *(float4*)(g_A + node * 64 + j) = o;
            } else {
                o.x = acc[i][0]; o.y = acc[i][1];
                o.z = acc[i][2]; o.w = acc[i][3];
                *(float4*)(g_B + node * 64 + (j - 64)) = o;
            }
        }
    }
}

// ---------------------------------------------------------------------------
// Edge kernel v4: 128 threads / 64-edge tiles / 4 blocks-per-SM.
//  - warp (rh, nh): rows rh*32..+32, cols nh*32..+32
//  - B fragments (4ks x 2nq2 hi/lo + bias hi/lo x 2) in registers, loaded once
//  - gather: 16 threads per edge row (coalesced 256B), idx broadcast via L1
//  - 2 __syncthreads per tile
// K layout: 0..63 data, 64 = ones (bias), 65..79 zero pad.
// ---------------------------------------------------------------------------
#define HSTR 88
#define OFF_HH 0                        // 64*88*2 = 11264
#define OFF_HL 11264                    // 11264
#define EDGE_SMEM 22784                 // 22528 + pad

__global__ void __launch_bounds__(128, 4)
edge_kernel(const int* __restrict__ ei, const float* __restrict__ W2,
            const float* __restrict__ b2, float* __restrict__ out) {
    __nv_bfloat16* hh = (__nv_bfloat16*)(dynsm + OFF_HH);
    __nv_bfloat16* hl = (__nv_bfloat16*)(dynsm + OFF_HL);

    const int t = threadIdx.x;
    const int w = t >> 5;
    const int rh = w >> 1;         // row half-group: rows rh*32..+32
    const int nh = w & 1;          // col half: cols nh*32..+32

    // ---- stage W2 hi/lo into the h planes (reused), load B frags, free ----
    if (t < 64) {
        int j = t;
#pragma unroll
        for (int k = 0; k < 64; k++) {
            float f = __ldg(W2 + j * 64 + k);
            __nv_bfloat16 hi = __float2bfloat16(f);
            hh[j * HSTR + k] = hi;
            hl[j * HSTR + k] = __float2bfloat16(f - __bfloat162float(hi));
        }
        float bf = __ldg(b2 + j);
        __nv_bfloat16 bh = __float2bfloat16(bf);
        hh[j * HSTR + 64] = bh;
        hl[j * HSTR + 64] = __float2bfloat16(bf - __bfloat162float(bh));
#pragma unroll
        for (int k = 65; k < 80; k++) {
            hh[j * HSTR + k] = __float2bfloat16(0.f);
            hl[j * HSTR + k] = __float2bfloat16(0.f);
        }
    }
    __syncthreads();

    wmma::fragment<wmma::matrix_b, 16, 16, 16, __nv_bfloat16, wmma::col_major>
        Bh[4][2], Bl[4][2], Bbh[2], Bbl[2];
#pragma unroll
    for (int ks = 0; ks < 4; ks++)
#pragma unroll
        for (int q = 0; q < 2; q++) {
            int j0 = (nh * 32 + q * 16) * HSTR;
            wmma::load_matrix_sync(Bh[ks][q], hh + j0 + ks * 16, HSTR);
            wmma::load_matrix_sync(Bl[ks][q], hl + j0 + ks * 16, HSTR);
        }
#pragma unroll
    for (int q = 0; q < 2; q++) {
        int j0 = (nh * 32 + q * 16) * HSTR;
        wmma::load_matrix_sync(Bbh[q], hh + j0 + 64, HSTR);
        wmma::load_matrix_sync(Bbl[q], hl + j0 + 64, HSTR);
    }
    __syncthreads();

    // ---- one-time: h pad columns (64 = ones, 65..79 = zero) ----
    if (t < 64) {
        hh[t * HSTR + 64] = __float2bfloat16(1.f);
        hl[t * HSTR + 64] = __float2bfloat16(0.f);
#pragma unroll
        for (int k = 65; k < 80; k++) {
            hh[t * HSTR + k] = __float2bfloat16(0.f);
            hl[t * HSTR + k] = __float2bfloat16(0.f);
        }
    }
    __syncthreads();

    const int grp = t >> 4;        // 8 groups of 16 threads
    const int g   = t & 15;        // float4 index within the 64-float row

    for (int tile = blockIdx.x; tile < NT64; tile += gridDim.x) {
        // ---- gather: 8 passes x 8 edge rows; idx broadcast within group ----
#pragma unroll
        for (int p = 0; p < 8; p++) {
            int edge = p * 8 + grp;
            int r = __ldg(ei + tile * 64 + edge);
            int c = __ldg(ei + EE + tile * 64 + edge);
            float4 a = __ldg((const float4*)(g_A + (size_t)r * 64) + g);
            float4 b = __ldg((const float4*)(g_B + (size_t)c * 64) + g);
            float f0 = fmaxf(a.x + b.x, 0.f);
            float f1 = fmaxf(a.y + b.y, 0.f);
            float f2 = fmaxf(a.z + b.z, 0.f);
            float f3 = fmaxf(a.w + b.w, 0.f);
            __nv_bfloat16 h0 = __float2bfloat16(f0), h1 = __float2bfloat16(f1);
            __nv_bfloat16 h2 = __float2bfloat16(f2), h3 = __float2bfloat16(f3);
            uint2 hi = make_uint2(pack_bf2(h0, h1), pack_bf2(h2, h3));
            uint2 lo = make_uint2(
                pack_bf2(__float2bfloat16(f0 - __bfloat162float(h0)),
                         __float2bfloat16(f1 - __bfloat162float(h1))),
                pack_bf2(__float2bfloat16(f2 - __bfloat162float(h2)),
                         __float2bfloat16(f3 - __bfloat162float(h3))));
            *(uint2*)(hh + edge * HSTR + g * 4) = hi;
            *(uint2*)(hl + edge * HSTR + g * 4) = lo;
        }
        __syncthreads();

        // ---- compute: warp (rh, nh); 2 sequential 16-row blocks ----
#pragma unroll
        for (int rbp = 0; rbp < 2; rbp++) {
            int rows = rh * 32 + rbp * 16;

            wmma::fragment<wmma::accumulator, 16, 16, 16, float> acc0, acc1;
            wmma::fill_fragment(acc0, 0.f);
            wmma::fill_fragment(acc1, 0.f);

            wmma::fragment<wmma::matrix_a, 16, 16, 16, __nv_bfloat16, wmma::row_major> ah, al;

#pragma unroll
            for (int ks = 0; ks < 4; ks++) {
                wmma::load_matrix_sync(ah, hh + rows * HSTR + ks * 16, HSTR);
                wmma::load_matrix_sync(al, hl + rows * HSTR + ks * 16, HSTR);
                wmma::mma_sync(acc0, ah, Bh[ks][0], acc0);
                wmma::mma_sync(acc1, ah, Bh[ks][1], acc1);
                wmma::mma_sync(acc0, ah, Bl[ks][0], acc0);
                wmma::mma_sync(acc1, ah, Bl[ks][1], acc1);
                wmma::mma_sync(acc0, al, Bh[ks][0], acc0);
                wmma::mma_sync(acc1, al, Bh[ks][1], acc1);
            }
            // bias block (ones column x b2 rows)
            wmma::load_matrix_sync(ah, hh + rows * HSTR + 64, HSTR);
            wmma::mma_sync(acc0, ah, Bbh[0], acc0);
            wmma::mma_sync(acc1, ah, Bbh[1], acc1);
            wmma::mma_sync(acc0, ah, Bbl[0], acc0);
            wmma::mma_sync(acc1, ah, Bbl[1], acc1);

#pragma unroll
            for (int i = 0; i < acc0.num_elements; i++) {
                acc0.x[i] = fmaxf(acc0.x[i], 0.f);
                acc1.x[i] = fmaxf(acc1.x[i], 0.f);
            }
            float* op = out + (size_t)(tile * 64 + rows) * 64 + nh * 32;
            wmma::store_matrix_sync(op, acc0, 64, wmma::mem_row_major);
            wmma::store_matrix_sync(op + 16, acc1, 64, wmma::mem_row_major);
        }
        __syncthreads();   // compute done before next tile's gather overwrites
    }
}

// ---------------------------------------------------------------------------
extern "C" void kernel_launch(void* const* d_in, const int* in_sizes, int n_in,
                              void* d_out, int out_size) {
    const float* x  = (const float*)d_in[0];
    const int*   ei = (const int*)d_in[1];     // int32 (JAX x64 disabled)
    const float* W1 = (const float*)d_in[2];
    const float* b1 = (const float*)d_in[3];
    const float* W2 = (const float*)d_in[4];
    const float* b2 = (const float*)d_in[5];
    float*       out = (float*)d_out;

    cudaFuncSetAttribute(pre_kernel,
                         cudaFuncAttributeMaxDynamicSharedMemorySize, PRE_SMEM);
    cudaFuncSetAttribute(edge_kernel,
                         cudaFuncAttributeMaxDynamicSharedMemorySize, EDGE_SMEM);

    pre_kernel<<<(NN + 127) / 128, 512, PRE_SMEM>>>(x, W1, b1);
    edge_kernel<<<592, 128, EDGE_SMEM>>>(ei, W2, b2, out);
}

// round 12
// speedup vs baseline: 2.8345x; 1.2274x over previous
#include <cuda_runtime.h>
#include <cuda_bf16.h>
#include <mma.h>
#include <cstdint>

using namespace nvcuda;

#define NN 100000
#define NN_PAD 100096        // 782 * 128, store-tail padding
#define EE 1600000
#define NT64 (EE / 64)       // 25000 64-edge tiles, exact
#define NPT 782              // node tiles of 128

__device__ __align__(256) float g_A[NN_PAD * 64];   // (W1a - W1b) @ x[n] + b1
__device__ __align__(256) float g_B[NN_PAD * 64];   // W1b @ x[n]

extern __shared__ __align__(16) char dynsm[];

static __device__ __forceinline__ uint32_t pack_bf2(__nv_bfloat16 a, __nv_bfloat16 b) {
    __nv_bfloat162 v = __halves2bfloat162(a, b);
    return *reinterpret_cast<uint32_t*>(&v);
}

// ---------------------------------------------------------------------------
// Pre kernel (wmma): A/B tables = x @ W1c + bias, bf16 hi/lo 3-term split.
// Tile = 128 nodes. 256 threads, warp (rh in 2, nh in 4): rows rh*64..+64,
// cols nh*32..+32 (nh<2 -> g_A, else g_B). No relu. Bias via ones column.
// K layout: 0..63 data, 64 = ones/bias, 65..79 zero pad.
// ---------------------------------------------------------------------------
#define PHSTR 88
#define PPLANE 22528                         // 128*88*2 bytes
#define PRE_SMEM (2 * PPLANE)                // 45056

__global__ void __launch_bounds__(256)
pre_kernel(const float* __restrict__ x, const float* __restrict__ W1,
           const float* __restrict__ b1) {
    __nv_bfloat16* ph = (__nv_bfloat16*)(dynsm);
    __nv_bfloat16* pl = (__nv_bfloat16*)(dynsm + PPLANE);

    const int t = threadIdx.x;
    const int w = t >> 5;
    const int rh = w >> 2;         // 0..1: rows rh*64..+64
    const int nh = w & 3;          // 0..3: cols nh*32..+32 (global j)

    // ---- stage W1c hi/lo into planes (col j = B-operand row) ----
    {
        int j = t & 127, kh = t >> 7;   // 2 threads per column
        if (kh == 0) {
#pragma unroll
            for (int k = 0; k < 32; k++) {
                float f = (j < 64)
                    ? __ldg(W1 + j * 128 + k) - __ldg(W1 + j * 128 + 64 + k)
                    : __ldg(W1 + (j - 64) * 128 + 64 + k);
                __nv_bfloat16 hi = __float2bfloat16(f);
                ph[j * PHSTR + k] = hi;
                pl[j * PHSTR + k] = __float2bfloat16(f - __bfloat162float(hi));
            }
        } else {
#pragma unroll
            for (int k = 32; k < 64; k++) {
                float f = (j < 64)
                    ? __ldg(W1 + j * 128 + k) - __ldg(W1 + j * 128 + 64 + k)
                    : __ldg(W1 + (j - 64) * 128 + 64 + k);
                __nv_bfloat16 hi = __float2bfloat16(f);
                ph[j * PHSTR + k] = hi;
                pl[j * PHSTR + k] = __float2bfloat16(f - __bfloat162float(hi));
            }
            float bf = (j < 64) ? __ldg(b1 + j) : 0.f;
            __nv_bfloat16 bh = __float2bfloat16(bf);
            ph[j * PHSTR + 64] = bh;
            pl[j * PHSTR + 64] = __float2bfloat16(bf - __bfloat162float(bh));
#pragma unroll
            for (int k = 65; k < 80; k++) {
                ph[j * PHSTR + k] = __float2bfloat16(0.f);
                pl[j * PHSTR + k] = __float2bfloat16(0.f);
            }
        }
    }
    __syncthreads();

    // ---- hoist W1c fragments into registers (per warp: 20 frags) ----
    wmma::fragment<wmma::matrix_b, 16, 16, 16, __nv_bfloat16, wmma::col_major>
        Bh[4][2], Bl[4][2], Bbh[2], Bbl[2];
#pragma unroll
    for (int ks = 0; ks < 4; ks++)
#pragma unroll
        for (int q = 0; q < 2; q++) {
            int j0 = (nh * 32 + q * 16) * PHSTR;
            wmma::load_matrix_sync(Bh[ks][q], ph + j0 + ks * 16, PHSTR);
            wmma::load_matrix_sync(Bl[ks][q], pl + j0 + ks * 16, PHSTR);
        }
#pragma unroll
    for (int q = 0; q < 2; q++) {
        int j0 = (nh * 32 + q * 16) * PHSTR;
        wmma::load_matrix_sync(Bbh[q], ph + j0 + 64, PHSTR);
        wmma::load_matrix_sync(Bbl[q], pl + j0 + 64, PHSTR);
    }
    __syncthreads();

    // ---- pad columns for x rows (64 = ones, 65..79 = zero), once ----
    if (t < 128) {
        ph[t * PHSTR + 64] = __float2bfloat16(1.f);
        pl[t * PHSTR + 64] = __float2bfloat16(0.f);
#pragma unroll
        for (int k = 65; k < 80; k++) {
            ph[t * PHSTR + k] = __float2bfloat16(0.f);
            pl[t * PHSTR + k] = __float2bfloat16(0.f);
        }
    }

    const int xr = t >> 4;         // 16 rows per pass
    const int g  = t & 15;

    for (int tile = blockIdx.x; tile < NPT; tile += gridDim.x) {
        int node0 = tile * 128;
        __syncthreads();           // frags/pads ready; prev tile consumed

        // ---- stage x tile: hi/lo split (coalesced, 8 passes) ----
#pragma unroll
        for (int p = 0; p < 8; p++) {
            int row = p * 16 + xr;
            int node = node0 + row;
            float4 v = make_float4(0.f, 0.f, 0.f, 0.f);
            if (node < NN) v = __ldg((const float4*)(x + (size_t)node * 64) + g);
            __nv_bfloat16 h0 = __float2bfloat16(v.x), h1 = __float2bfloat16(v.y);
            __nv_bfloat16 h2 = __float2bfloat16(v.z), h3 = __float2bfloat16(v.w);
            uint2 hi = make_uint2(pack_bf2(h0, h1), pack_bf2(h2, h3));
            uint2 lo = make_uint2(
                pack_bf2(__float2bfloat16(v.x - __bfloat162float(h0)),
                         __float2bfloat16(v.y - __bfloat162float(h1))),
                pack_bf2(__float2bfloat16(v.z - __bfloat162float(h2)),
                         __float2bfloat16(v.w - __bfloat162float(h3))));
            *(uint2*)(ph + row * PHSTR + g * 4) = hi;
            *(uint2*)(pl + row * PHSTR + g * 4) = lo;
        }
        __syncthreads();

        // ---- compute: warp (rh, nh); 4 sequential 16-row blocks ----
        float* tbase = (nh < 2) ? (g_A + nh * 32) : (g_B + (nh - 2) * 32);
#pragma unroll
        for (int rbp = 0; rbp < 4; rbp++) {
            int rows = rh * 64 + rbp * 16;

            wmma::fragment<wmma::accumulator, 16, 16, 16, float> acc0, acc1;
            wmma::fill_fragment(acc0, 0.f);
            wmma::fill_fragment(acc1, 0.f);

            wmma::fragment<wmma::matrix_a, 16, 16, 16, __nv_bfloat16, wmma::row_major> ah, al;

#pragma unroll
            for (int ks = 0; ks < 4; ks++) {
                wmma::load_matrix_sync(ah, ph + rows * PHSTR + ks * 16, PHSTR);
                wmma::load_matrix_sync(al, pl + rows * PHSTR + ks * 16, PHSTR);
                wmma::mma_sync(acc0, ah, Bh[ks][0], acc0);
                wmma::mma_sync(acc1, ah, Bh[ks][1], acc1);
                wmma::mma_sync(acc0, ah, Bl[ks][0], acc0);
                wmma::mma_sync(acc1, ah, Bl[ks][1], acc1);
                wmma::mma_sync(acc0, al, Bh[ks][0], acc0);
                wmma::mma_sync(acc1, al, Bh[ks][1], acc1);
            }
            wmma::load_matrix_sync(ah, ph + rows * PHSTR + 64, PHSTR);
            wmma::mma_sync(acc0, ah, Bbh[0], acc0);
            wmma::mma_sync(acc1, ah, Bbh[1], acc1);
            wmma::mma_sync(acc0, ah, Bbl[0], acc0);
            wmma::mma_sync(acc1, ah, Bbl[1], acc1);

            float* op = tbase + (size_t)(node0 + rows) * 64;
            wmma::store_matrix_sync(op, acc0, 64, wmma::mem_row_major);
            wmma::store_matrix_sync(op + 16, acc1, 64, wmma::mem_row_major);
        }
    }
}

// ---------------------------------------------------------------------------
// Edge kernel v4 (unchanged from R11): 128 threads / 64-edge tiles / 4 blk/SM.
// ---------------------------------------------------------------------------
#define HSTR 88
#define OFF_HH 0                        // 64*88*2 = 11264
#define OFF_HL 11264                    // 11264
#define EDGE_SMEM 22784                 // 22528 + pad

__global__ void __launch_bounds__(128, 4)
edge_kernel(const int* __restrict__ ei, const float* __restrict__ W2,
            const float* __restrict__ b2, float* __restrict__ out) {
    __nv_bfloat16* hh = (__nv_bfloat16*)(dynsm + OFF_HH);
    __nv_bfloat16* hl = (__nv_bfloat16*)(dynsm + OFF_HL);

    const int t = threadIdx.x;
    const int w = t >> 5;
    const int rh = w >> 1;         // rows rh*32..+32
    const int nh = w & 1;          // cols nh*32..+32

    if (t < 64) {
        int j = t;
#pragma unroll
        for (int k = 0; k < 64; k++) {
            float f = __ldg(W2 + j * 64 + k);
            __nv_bfloat16 hi = __float2bfloat16(f);
            hh[j * HSTR + k] = hi;
            hl[j * HSTR + k] = __float2bfloat16(f - __bfloat162float(hi));
        }
        float bf = __ldg(b2 + j);
        __nv_bfloat16 bh = __float2bfloat16(bf);
        hh[j * HSTR + 64] = bh;
        hl[j * HSTR + 64] = __float2bfloat16(bf - __bfloat162float(bh));
#pragma unroll
        for (int k = 65; k < 80; k++) {
            hh[j * HSTR + k] = __float2bfloat16(0.f);
            hl[j * HSTR + k] = __float2bfloat16(0.f);
        }
    }
    __syncthreads();

    wmma::fragment<wmma::matrix_b, 16, 16, 16, __nv_bfloat16, wmma::col_major>
        Bh[4][2], Bl[4][2], Bbh[2], Bbl[2];
#pragma unroll
    for (int ks = 0; ks < 4; ks++)
#pragma unroll
        for (int q = 0; q < 2; q++) {
            int j0 = (nh * 32 + q * 16) * HSTR;
            wmma::load_matrix_sync(Bh[ks][q], hh + j0 + ks * 16, HSTR);
            wmma::load_matrix_sync(Bl[ks][q], hl + j0 + ks * 16, HSTR);
        }
#pragma unroll
    for (int q = 0; q < 2; q++) {
        int j0 = (nh * 32 + q * 16) * HSTR;
        wmma::load_matrix_sync(Bbh[q], hh + j0 + 64, HSTR);
        wmma::load_matrix_sync(Bbl[q], hl + j0 + 64, HSTR);
    }
    __syncthreads();

    if (t < 64) {
        hh[t * HSTR + 64] = __float2bfloat16(1.f);
        hl[t * HSTR + 64] = __float2bfloat16(0.f);
#pragma unroll
        for (int k = 65; k < 80; k++) {
            hh[t * HSTR + k] = __float2bfloat16(0.f);
            hl[t * HSTR + k] = __float2bfloat16(0.f);
        }
    }
    __syncthreads();

    const int grp = t >> 4;
    const int g   = t & 15;

    for (int tile = blockIdx.x; tile < NT64; tile += gridDim.x) {
#pragma unroll
        for (int p = 0; p < 8; p++) {
            int edge = p * 8 + grp;
            int r = __ldg(ei + tile * 64 + edge);
            int c = __ldg(ei + EE + tile * 64 + edge);
            float4 a = __ldg((const float4*)(g_A + (size_t)r * 64) + g);
            float4 b = __ldg((const float4*)(g_B + (size_t)c * 64) + g);
            float f0 = fmaxf(a.x + b.x, 0.f);
            float f1 = fmaxf(a.y + b.y, 0.f);
            float f2 = fmaxf(a.z + b.z, 0.f);
            float f3 = fmaxf(a.w + b.w, 0.f);
            __nv_bfloat16 h0 = __float2bfloat16(f0), h1 = __float2bfloat16(f1);
            __nv_bfloat16 h2 = __float2bfloat16(f2), h3 = __float2bfloat16(f3);
            uint2 hi = make_uint2(pack_bf2(h0, h1), pack_bf2(h2, h3));
            uint2 lo = make_uint2(
                pack_bf2(__float2bfloat16(f0 - __bfloat162float(h0)),
                         __float2bfloat16(f1 - __bfloat162float(h1))),
                pack_bf2(__float2bfloat16(f2 - __bfloat162float(h2)),
                         __float2bfloat16(f3 - __bfloat162float(h3))));
            *(uint2*)(hh + edge * HSTR + g * 4) = hi;
            *(uint2*)(hl + edge * HSTR + g * 4) = lo;
        }
        __syncthreads();

#pragma unroll
        for (int rbp = 0; rbp < 2; rbp++) {
            int rows = rh * 32 + rbp * 16;

            wmma::fragment<wmma::accumulator, 16, 16, 16, float> acc0, acc1;
            wmma::fill_fragment(acc0, 0.f);
            wmma::fill_fragment(acc1, 0.f);

            wmma::fragment<wmma::matrix_a, 16, 16, 16, __nv_bfloat16, wmma::row_major> ah, al;

#pragma unroll
            for (int ks = 0; ks < 4; ks++) {
                wmma::load_matrix_sync(ah, hh + rows * HSTR + ks * 16, HSTR);
                wmma::load_matrix_sync(al, hl + rows * HSTR + ks * 16, HSTR);
                wmma::mma_sync(acc0, ah, Bh[ks][0], acc0);
                wmma::mma_sync(acc1, ah, Bh[ks][1], acc1);
                wmma::mma_sync(acc0, ah, Bl[ks][0], acc0);
                wmma::mma_sync(acc1, ah, Bl[ks][1], acc1);
                wmma::mma_sync(acc0, al, Bh[ks][0], acc0);
                wmma::mma_sync(acc1, al, Bh[ks][1], acc1);
            }
            wmma::load_matrix_sync(ah, hh + rows * HSTR + 64, HSTR);
            wmma::mma_sync(acc0, ah, Bbh[0], acc0);
            wmma::mma_sync(acc1, ah, Bbh[1], acc1);
            wmma::mma_sync(acc0, ah, Bbl[0], acc0);
            wmma::mma_sync(acc1, ah, Bbl[1], acc1);

#pragma unroll
            for (int i = 0; i < acc0.num_elements; i++) {
                acc0.x[i] = fmaxf(acc0.x[i], 0.f);
                acc1.x[i] = fmaxf(acc1.x[i], 0.f);
            }
            float* op = out + (size_t)(tile * 64 + rows) * 64 + nh * 32;
            wmma::store_matrix_sync(op, acc0, 64, wmma::mem_row_major);
            wmma::store_matrix_sync(op + 16, acc1, 64, wmma::mem_row_major);
        }
        __syncthreads();
    }
}

// ---------------------------------------------------------------------------
extern "C" void kernel_launch(void* const* d_in, const int* in_sizes, int n_in,
                              void* d_out, int out_size) {
    const float* x  = (const float*)d_in[0];
    const int*   ei = (const int*)d_in[1];     // int32 (JAX x64 disabled)
    const float* W1 = (const float*)d_in[2];
    const float* b1 = (const float*)d_in[3];
    const float* W2 = (const float*)d_in[4];
    const float* b2 = (const float*)d_in[5];
    float*       out = (float*)d_out;

    cudaFuncSetAttribute(pre_kernel,
                         cudaFuncAttributeMaxDynamicSharedMemorySize, PRE_SMEM);
    cudaFuncSetAttribute(edge_kernel,
                         cudaFuncAttributeMaxDynamicSharedMemorySize, EDGE_SMEM);

    pre_kernel<<<296, 256, PRE_SMEM>>>(x, W1, b1);
    edge_kernel<<<592, 128, EDGE_SMEM>>>(ei, W2, b2, out);
}